// round 16
// baseline (speedup 1.0000x reference)
#include <cuda_runtime.h>
#include <math.h>

#define NB    8
#define NPK   80
#define NL    100000
#define NTOP  200
#define NANG  90
#define DIST  0.2f
#define EPSF  1e-12f
#define BINS  81
#define SB    512
#define NLB   196          // ceil(NL/SB)
#define MAGICF 12582912.0f // 1.5*2^23: (x+M)-M == rintf(x) for |x| < 2^22

typedef unsigned long long ull;

// ---- scratch (no allocation allowed) ----
__device__ unsigned char g_score[NB * NL + 128];
__device__ int           g_hist[NB * BINS];        // zero-init; k_select consumes+rezeros
__device__ int           g_topidx[NB * NTOP];
__device__ __align__(16) float g_pre[NB * NTOP * 28];  // cells[9],A[9],AA[9],pad
__device__ float         g_trig[96 * 2];            // sv, cv per angle (idempotent writes)
__device__ ull           g_key[NB * NTOP];
__device__ unsigned      g_done_c[NB];              // zero-init; last cand-block consumes+rezeros

// packed f32x2 helpers
#define MUL2(d,a,b)   asm("mul.rn.f32x2 %0,%1,%2;"    : "=l"(d) : "l"(a),"l"(b))
#define ADD2(d,a,b)   asm("add.rn.f32x2 %0,%1,%2;"    : "=l"(d) : "l"(a),"l"(b))
#define FMA2(d,a,b,c) asm("fma.rn.f32x2 %0,%1,%2,%3;" : "=l"(d) : "l"(a),"l"(b),"l"(c))
__device__ __forceinline__ ull pk2(float lo, float hi) {
    ull r; asm("mov.b64 %0,{%1,%2};" : "=l"(r) : "f"(lo), "f"(hi)); return r;
}
__device__ __forceinline__ float2 upk2(ull v) {
    float2 r; asm("mov.b64 {%0,%1},%2;" : "=f"(r.x), "=f"(r.y) : "l"(v)); return r;
}

// exact IEEE division (Markstein-1 with correctly-rounded reciprocal)
__device__ __forceinline__ float div_x(float a, float b) {
    float r = __frcp_rn(b);
    float q0 = a * r;
    return fmaf(r, fmaf(-b, q0, a), q0);
}
__device__ __forceinline__ float div_xr(float a, float b, float r) {
    float q0 = a * r;
    return fmaf(r, fmaf(-b, q0, a), q0);
}

// cofactor inverse matching the JAX reference (zero matrix if |det|<1e-10)
__device__ __forceinline__ void inv3(const float* M, float* o) {
    float a=M[0],b=M[1],c=M[2],d=M[3],e=M[4],f=M[5],g=M[6],h=M[7],i=M[8];
    float det = a*(e*i-f*h) - b*(d*i-f*g) + c*(d*h-e*g);
    float invd = (fabsf(det) >= 1e-10f) ? __frcp_rn(det) : 0.0f;
    o[0]=(e*i-f*h)*invd; o[1]=(c*h-b*i)*invd; o[2]=(b*f-c*e)*invd;
    o[3]=(f*g-d*i)*invd; o[4]=(a*i-c*g)*invd; o[5]=(c*d-a*f)*invd;
    o[6]=(d*h-e*g)*invd; o[7]=(b*g-a*h)*invd; o[8]=(a*e-b*d)*invd;
}

// ---- candidate construction, split so all call sites share arithmetic ----
__device__ __forceinline__ void make_prefix(const float* __restrict__ cell,
                                            float tx, float ty, float tz,
                                            float* cells, float* A2, float* AA) {
    float c00 = cell[0], c01 = cell[1], c02 = cell[2];
    float snn = sqrtf(c00*c00 + c01*c01 + c02*c02) + EPSF;
    float rsn = __frcp_rn(snn);
    float sx = div_xr(c00, snn, rsn), sy = div_xr(c01, snn, rsn), sz = div_xr(c02, snn, rsn);
    float tnn = sqrtf(tx*tx + ty*ty + tz*tz) + EPSF;
    float rtn = __frcp_rn(tnn);
    float ux = div_xr(tx, tnn, rtn), uy = div_xr(ty, tnn, rtn), uz = div_xr(tz, tnn, rtn);
    float Vx = sy*uz - sz*uy;
    float Vy = sz*ux - sx*uz;
    float Vz = sx*uy - sy*ux;
    float C  = sx*ux + sy*uy + sz*uz;
    float S2 = Vx*Vx + Vy*Vy + Vz*Vz;
    float K[9] = {0.0f,-Vz,Vy,  Vz,0.0f,-Vx,  -Vy,Vx,0.0f};
    float KK[9];
    #pragma unroll
    for (int r = 0; r < 3; r++)
        #pragma unroll
        for (int c2 = 0; c2 < 3; c2++)
            KK[r*3+c2] = K[r*3+0]*K[0*3+c2] + K[r*3+1]*K[1*3+c2] + K[r*3+2]*K[2*3+c2];
    float fac = div_x(1.0f - C, S2 + EPSF);
    float R0[9];
    #pragma unroll
    for (int i = 0; i < 9; i++) {
        float Ii = (i == 0 || i == 4 || i == 8) ? 1.0f : 0.0f;
        R0[i] = (Ii + K[i]) + fac * KK[i];
    }
    #pragma unroll
    for (int r = 0; r < 3; r++)
        #pragma unroll
        for (int i = 0; i < 3; i++)
            cells[r*3+i] = R0[i*3+0]*cell[r*3+0] + R0[i*3+1]*cell[r*3+1] + R0[i*3+2]*cell[r*3+2];
    A2[0]=0.0f; A2[1]=-uz; A2[2]=uy;  A2[3]=uz; A2[4]=0.0f; A2[5]=-ux;  A2[6]=-uy; A2[7]=ux; A2[8]=0.0f;
    #pragma unroll
    for (int r = 0; r < 3; r++)
        #pragma unroll
        for (int c2 = 0; c2 < 3; c2++)
            AA[r*3+c2] = A2[r*3+0]*A2[0*3+c2] + A2[r*3+1]*A2[1*3+c2] + A2[r*3+2]*A2[2*3+c2];
}

__device__ __forceinline__ void cand_from_prefix(const float* cells, const float* A2,
                                                 const float* AA, float sv, float cv,
                                                 float* cd) {
    float Rr[9];
    #pragma unroll
    for (int i = 0; i < 9; i++) {
        float Ii = (i == 0 || i == 4 || i == 8) ? 1.0f : 0.0f;
        Rr[i] = (Ii + sv * A2[i]) + cv * AA[i];
    }
    #pragma unroll
    for (int r = 0; r < 3; r++)
        #pragma unroll
        for (int i = 0; i < 3; i++)
            cd[r*3+i] = Rr[i*3+0]*cells[r*3+0] + Rr[i*3+1]*cells[r*3+1] + Rr[i*3+2]*cells[r*3+2];
}

__device__ __forceinline__ void make_cand(const float* __restrict__ cell,
                                          float tx, float ty, float tz,
                                          int a, float* cd) {
    float cells[9], A2[9], AA[9];
    make_prefix(cell, tx, ty, tz, cells, A2, AA);
    float alpha = (6.2831855f * (float)a) / 90.0f;
    cand_from_prefix(cells, A2, AA, sinf(alpha), 1.0f - cosf(alpha), cd);
}

// ============================================================
// Kernel 1: integer-ness score + folded histogram.
// ============================================================
__global__ void __launch_bounds__(SB, 4)
k_score(const float* __restrict__ peaks,
        const float* __restrict__ cell,
        const float* __restrict__ lat) {
    __shared__ __align__(16) float sx[NPK];
    __shared__ __align__(16) float sy[NPK];
    __shared__ __align__(16) float sz[NPK];
    __shared__ int shist[BINS];
    int tid = threadIdx.x;
    int b = blockIdx.y;

    float scale0 = sqrtf(cell[0]*cell[0] + cell[1]*cell[1] + cell[2]*cell[2]);
    if (tid < NPK) {
        const float* p = peaks + (b * NPK + tid) * 3;
        sx[tid] = p[0] / scale0;
        sy[tid] = p[1] / scale0;
        sz[tid] = p[2] / scale0;
    }
    if (tid >= 128 && tid < 128 + BINS) shist[tid - 128] = 0;
    __syncthreads();

    int l = blockIdx.x * SB + tid;
    bool act = (l < NL);
    float lx = 0.f, ly = 0.f, lz = 0.f;
    if (act) { lx = lat[l*3+0]; ly = lat[l*3+1]; lz = lat[l*3+2]; }
    ull LX = pk2(lx, lx), LY = pk2(ly, ly), LZ = pk2(lz, lz);
    ull MG = pk2(MAGICF, MAGICF), MGN = pk2(-MAGICF, -MAGICF), N1 = pk2(-1.0f, -1.0f);

    const ulonglong2* px = (const ulonglong2*)sx;
    const ulonglong2* py = (const ulonglong2*)sy;
    const ulonglong2* pz = (const ulonglong2*)sz;
    int c0 = 0, c1 = 0, c2 = 0, c3 = 0;
    #pragma unroll
    for (int j = 0; j < NPK/4; j++) {
        ulonglong2 X = px[j], Y = py[j], Z = pz[j];
        ull qa, qb;
        MUL2(qa, X.x, LX); FMA2(qa, Y.x, LY, qa); FMA2(qa, Z.x, LZ, qa);
        MUL2(qb, X.y, LX); FMA2(qb, Y.y, LY, qb); FMA2(qb, Z.y, LZ, qb);
        ull ra, rb, da, db;
        ADD2(ra, qa, MG); ADD2(ra, ra, MGN);
        ADD2(rb, qb, MG); ADD2(rb, rb, MGN);
        FMA2(da, ra, N1, qa);
        FMA2(db, rb, N1, qb);
        float2 fa = upk2(da), fb = upk2(db);
        c0 += (fabsf(fa.x) < DIST) ? 1 : 0;
        c1 += (fabsf(fa.y) < DIST) ? 1 : 0;
        c2 += (fabsf(fb.x) < DIST) ? 1 : 0;
        c3 += (fabsf(fb.y) < DIST) ? 1 : 0;
    }
    int cnt = (c0 + c1) + (c2 + c3);
    if (act) {
        g_score[b * NL + l] = (unsigned char)cnt;
        atomicAdd(&shist[cnt], 1);
    }
    __syncthreads();
    if (tid < BINS) {
        int v = shist[tid];
        if (v) atomicAdd(&g_hist[b * BINS + tid], v);
    }
}

// ============================================================
// Kernel 2: exact top-200 per batch + candidate-prefix precompute.
// ============================================================
__global__ void k_select(const float* __restrict__ cell,
                         const float* __restrict__ lat) {
    int b = blockIdx.x;
    int tid = threadIdx.x;
    int lane = tid & 31, wid = tid >> 5;
    __shared__ int sh[BINS];
    __shared__ int sel[256];
    __shared__ int warpsum[32];
    __shared__ int s_ss, s_na, s_ne, gtc;

    if (tid < BINS) { sh[tid] = g_hist[b * BINS + tid]; g_hist[b * BINS + tid] = 0; }
    if (tid == 0) gtc = 0;
    __syncthreads();
    if (tid == 0) {
        int cum = 0, na = 0, s;
        for (s = 80; s >= 0; s--) {
            na = cum;
            cum += sh[s];
            if (cum >= NTOP) break;
        }
        s_ss = s; s_na = na; s_ne = NTOP - na;
    }
    __syncthreads();
    int ss = s_ss, na = s_na, ne = s_ne;
    unsigned ssx4 = (unsigned)ss * 0x01010101u;

    const uint4* gp = (const uint4*)(g_score + (size_t)b * NL);
    bool own  = (tid < 782);
    bool full = (tid < 781);

    int eqc = 0;
    if (own) {
        #pragma unroll
        for (int u = 0; u < 8; u++) {
            uint4 v = gp[tid * 8 + u];
            unsigned ws[4] = {v.x, v.y, v.z, v.w};
            #pragma unroll
            for (int w = 0; w < 4; w++) {
                unsigned word = ws[w];
                if (full) {
                    unsigned gtm = __vcmpgtu4(word, ssx4);
                    if (gtm) {
                        #pragma unroll
                        for (int j = 0; j < 4; j++) {
                            if ((gtm >> (8*j)) & 0xff) {
                                int s = (word >> (8*j)) & 0xff;
                                int idx = tid * 128 + u * 16 + w * 4 + j;
                                int slot = atomicAdd(&gtc, 1);
                                sel[slot] = ((80 - s) << 17) | idx;
                            }
                        }
                    }
                    eqc += __popc(__vcmpeq4(word, ssx4)) >> 3;
                } else {
                    #pragma unroll
                    for (int j = 0; j < 4; j++) {
                        int idx = tid * 128 + u * 16 + w * 4 + j;
                        int s = (word >> (8*j)) & 0xff;
                        if (idx < NL) {
                            if (s > ss) {
                                int slot = atomicAdd(&gtc, 1);
                                sel[slot] = ((80 - s) << 17) | idx;
                            }
                            eqc += (s == ss) ? 1 : 0;
                        }
                    }
                }
            }
        }
    }
    int v = eqc;
    #pragma unroll
    for (int off = 1; off < 32; off <<= 1) {
        int u = __shfl_up_sync(0xffffffffu, v, off);
        if (lane >= off) v += u;
    }
    if (lane == 31) warpsum[wid] = v;
    __syncthreads();
    if (tid < 32) {
        int x = warpsum[tid], y = x;
        #pragma unroll
        for (int off = 1; off < 32; off <<= 1) {
            int u = __shfl_up_sync(0xffffffffu, x, off);
            if (tid >= off) x += u;
        }
        warpsum[tid] = x - y;
    }
    __syncthreads();
    int rank = warpsum[wid] + (v - eqc);

    if (own && eqc > 0 && rank < ne) {
        #pragma unroll
        for (int u = 0; u < 8; u++) {
            uint4 vv = gp[tid * 8 + u];
            unsigned ws[4] = {vv.x, vv.y, vv.z, vv.w};
            #pragma unroll
            for (int w = 0; w < 4; w++) {
                unsigned word = ws[w];
                unsigned eqm = __vcmpeq4(word, ssx4);
                if (eqm) {
                    #pragma unroll
                    for (int j = 0; j < 4; j++) {
                        if ((eqm >> (8*j)) & 0xff) {
                            int idx = tid * 128 + u * 16 + w * 4 + j;
                            if (full || idx < NL) {
                                if (rank < ne) sel[na + rank] = ((80 - ss) << 17) | idx;
                                rank++;
                            }
                        }
                    }
                }
            }
        }
    }
    if (tid >= NTOP && tid < 256) sel[tid] = 0x7FFFFFFF;
    __syncthreads();

    for (int size = 2; size <= 256; size <<= 1) {
        for (int stride = size >> 1; stride > 0; stride >>= 1) {
            if (tid < 256) {
                int partner = tid ^ stride;
                if (partner > tid) {
                    bool up = ((tid & size) == 0);
                    int x = sel[tid], y = sel[partner];
                    if ((x > y) == up) { sel[tid] = y; sel[partner] = x; }
                }
            }
            __syncthreads();
        }
    }
    if (tid < NTOP) g_topidx[b * NTOP + tid] = sel[tid] & 0x1FFFF;

    // ---- candidate prefix precompute (cells, A, AA) for each selected k ----
    if (tid < NTOP) {
        int li = sel[tid] & 0x1FFFF;
        float tx = lat[li*3+0], ty = lat[li*3+1], tz = lat[li*3+2];
        float cells[9], A2[9], AA[9];
        make_prefix(cell, tx, ty, tz, cells, A2, AA);
        float* pre = g_pre + ((size_t)b * NTOP + tid) * 28;
        #pragma unroll
        for (int i = 0; i < 9; i++) {
            pre[i] = cells[i]; pre[9 + i] = A2[i]; pre[18 + i] = AA[i];
        }
        pre[27] = 0.0f;
    }
    // ---- angle trig table (idempotent identical writes across blocks) ----
    if (tid >= 256 && tid < 256 + 96) {
        int al = tid - 256;
        float alpha = (6.2831855f * (float)al) / 90.0f;
        g_trig[al*2+0] = sinf(alpha);
        g_trig[al*2+1] = 1.0f - cosf(alpha);
    }
}

// ============================================================
// refine for one batch: warp-collective COLD path.
// __noinline__ keeps its register demand out of k_cand's hot path.
// ============================================================
__device__ __noinline__ void refine_batch(int b, int lane,
                             const float* __restrict__ peaks,
                             const float* __restrict__ cell,
                             const float* __restrict__ lat,
                             float* __restrict__ out, int out_size) {
    ull best = 0ull;
    for (int k = lane; k < NTOP; k += 32) {
        ull u = __ldcg(&g_key[b * NTOP + k]);
        if (u > best) best = u;
    }
    #pragma unroll
    for (int off = 16; off > 0; off >>= 1) {
        ull u = __shfl_xor_sync(0xffffffffu, best, off);
        if (u > best) best = u;
    }
    int scount = (int)(best >> 32);
    int m = (int)(0xFFFFFFFFu - (unsigned)(best & 0xFFFFFFFFull));
    int kw = m / NANG, aw = m % NANG;

    int li = g_topidx[b * NTOP + kw];
    float tx = lat[li*3+0], ty = lat[li*3+1], tz = lat[li*3+2];
    float B[9];
    make_cand(cell, tx, ty, tz, aw, B);

    int l16 = lane & 15;
    float Px[5], Py[5], Pz[5];
    #pragma unroll
    for (int r = 0; r < 5; r++) {
        const float* p = peaks + (b * NPK + l16 + 16 * r) * 3;
        Px[r] = p[0]; Py[r] = p[1]; Pz[r] = p[2];
    }

    const float thrs[5] = {0.02f, 0.015375f, 0.01075f, 0.006125f, 0.0015f};
    #pragma unroll 1
    for (int t = 0; t < 5; t++) {
        float I[9];
        inv3(B, I);
        float acc[15];
        #pragma unroll
        for (int i = 0; i < 15; i++) acc[i] = 0.0f;
        #pragma unroll
        for (int r = 0; r < 5; r++) {
            float p0 = Px[r], p1 = Py[r], p2 = Pz[r];
            float h0 = rintf(p0*I[0] + p1*I[3] + p2*I[6]);
            float h1 = rintf(p0*I[1] + p1*I[4] + p2*I[7]);
            float h2 = rintf(p0*I[2] + p1*I[5] + p2*I[8]);
            float q0 = h0*B[0] + h1*B[3] + h2*B[6] - p0;
            float q1 = h0*B[1] + h1*B[4] + h2*B[7] - p1;
            float q2 = h0*B[2] + h1*B[5] + h2*B[8] - p2;
            float resid = sqrtf(q0*q0 + q1*q1 + q2*q2);
            if (resid < thrs[t]) {
                acc[0]+=h0*h0; acc[1]+=h0*h1; acc[2]+=h0*h2;
                acc[3]+=h1*h1; acc[4]+=h1*h2; acc[5]+=h2*h2;
                acc[6]+=h0*p0;  acc[7]+=h0*p1;  acc[8]+=h0*p2;
                acc[9]+=h1*p0;  acc[10]+=h1*p1; acc[11]+=h1*p2;
                acc[12]+=h2*p0; acc[13]+=h2*p1; acc[14]+=h2*p2;
            }
        }
        #pragma unroll
        for (int off = 8; off > 0; off >>= 1)
            #pragma unroll
            for (int i = 0; i < 15; i++)
                acc[i] += __shfl_xor_sync(0xffffffffu, acc[i], off);
        float XtX[9] = {acc[0],acc[1],acc[2], acc[1],acc[3],acc[4], acc[2],acc[4],acc[5]};
        float IX[9];
        inv3(XtX, IX);
        float nB[9];
        #pragma unroll
        for (int r = 0; r < 3; r++)
            #pragma unroll
            for (int d2 = 0; d2 < 3; d2++)
                nB[r*3+d2] = IX[r*3+0]*acc[6+0*3+d2] + IX[r*3+1]*acc[6+1*3+d2] + IX[r*3+2]*acc[6+2*3+d2];
        #pragma unroll
        for (int i = 0; i < 9; i++) B[i] = nB[i];
    }

    if (lane == 0) {
        float bn[3], cn[3], dc = 0.0f;
        for (int r = 0; r < 3; r++) {
            bn[r] = sqrtf(B[r*3]*B[r*3] + B[r*3+1]*B[r*3+1] + B[r*3+2]*B[r*3+2]);
            cn[r] = sqrtf(cell[r*3]*cell[r*3] + cell[r*3+1]*cell[r*3+1] + cell[r*3+2]*cell[r*3+2]);
            dc = fmaxf(dc, fabsf(bn[r] - cn[r]));
        }
        float Bn[9], Cn[9];
        for (int r = 0; r < 3; r++)
            for (int i = 0; i < 3; i++) {
                Bn[r*3+i] = B[r*3+i] / (bn[r] + EPSF);
                Cn[r*3+i] = cell[r*3+i] / (cn[r] + EPSF);
            }
        const float todeg = 57.29577951308232f;
        float da = 0.0f;
        const int pi_[3] = {0, 0, 1};
        const int pj_[3] = {1, 2, 2};
        for (int q = 0; q < 3; q++) {
            int i = pi_[q], j = pj_[q];
            float db = Bn[i*3]*Bn[j*3] + Bn[i*3+1]*Bn[j*3+1] + Bn[i*3+2]*Bn[j*3+2];
            float dl = Cn[i*3]*Cn[j*3] + Cn[i*3+1]*Cn[j*3+1] + Cn[i*3+2]*Cn[j*3+2];
            db = fminf(fmaxf(db, -1.0f), 1.0f);
            dl = fminf(fmaxf(dl, -1.0f), 1.0f);
            float ab = acosf(db) * todeg;
            float ac = acosf(dl) * todeg;
            da = fmaxf(da, fabsf(ab - ac));
        }
        float pen = dc*dc*dc + da*da*da;

        for (int i = 0; i < 9; i++) out[b*9 + i] = B[i];
        if (out_size >= 88) {
            out[72 + b] = (float)scount;
            out[80 + b] = pen;
        }
    }
}

// ============================================================
// Kernel 3: candidate scoring (prefix from g_pre, trig from table),
// 2 k's per block (192 threads), + per-batch last-block refine.
// ============================================================
__global__ void __launch_bounds__(192, 6)
k_cand(const float* __restrict__ peaks,
       const float* __restrict__ cell,
       const float* __restrict__ lat,
       float* __restrict__ out, int out_size) {
    int b = blockIdx.y;
    int a = threadIdx.x;            // 0..191
    int kk = (a >= 96) ? 1 : 0;
    int al = a - 96 * kk;           // local angle 0..95 (90..95 garbage)
    int k  = blockIdx.x * 2 + kk;

    __shared__ __align__(16) float spx[NPK];
    __shared__ __align__(16) float spy[NPK];
    __shared__ __align__(16) float spz[NPK];
    __shared__ ull skey[192];
    __shared__ int s_last;

    if (a < NPK) {
        const float* p = peaks + (b * NPK + a) * 3;
        spx[a] = p[0]; spy[a] = p[1]; spz[a] = p[2];
    }

    const float4* pre4 = (const float4*)(g_pre + ((size_t)b * NTOP + k) * 28);
    float pr[28];
    #pragma unroll
    for (int i = 0; i < 7; i++) {
        float4 v = pre4[i];
        pr[i*4+0] = v.x; pr[i*4+1] = v.y; pr[i*4+2] = v.z; pr[i*4+3] = v.w;
    }
    float sv = g_trig[al*2+0];
    float cv = g_trig[al*2+1];
    float cd[9];
    cand_from_prefix(pr, pr + 9, pr + 18, sv, cv, cd);
    float iv[9];
    inv3(cd, iv);

    ull IV0 = pk2(iv[0], iv[0]), IV1 = pk2(iv[1], iv[1]), IV2 = pk2(iv[2], iv[2]);
    ull IV3 = pk2(iv[3], iv[3]), IV4 = pk2(iv[4], iv[4]), IV5 = pk2(iv[5], iv[5]);
    ull IV6 = pk2(iv[6], iv[6]), IV7 = pk2(iv[7], iv[7]), IV8 = pk2(iv[8], iv[8]);
    ull MG = pk2(MAGICF, MAGICF), MGN = pk2(-MAGICF, -MAGICF), N1 = pk2(-1.0f, -1.0f);

    __syncthreads();  // sp ready (uniform)

    const ulonglong2* px = (const ulonglong2*)spx;
    const ulonglong2* py = (const ulonglong2*)spy;
    const ulonglong2* pz = (const ulonglong2*)spz;
    int c0 = 0, c1 = 0, c2 = 0, c3 = 0;
    #pragma unroll 5
    for (int j = 0; j < NPK/4; j++) {
        ulonglong2 X = px[j], Y = py[j], Z = pz[j];
        ull h0a, h1a, h2a, h0b, h1b, h2b;
        MUL2(h0a, X.x, IV0); FMA2(h0a, Y.x, IV3, h0a); FMA2(h0a, Z.x, IV6, h0a);
        MUL2(h1a, X.x, IV1); FMA2(h1a, Y.x, IV4, h1a); FMA2(h1a, Z.x, IV7, h1a);
        MUL2(h2a, X.x, IV2); FMA2(h2a, Y.x, IV5, h2a); FMA2(h2a, Z.x, IV8, h2a);
        MUL2(h0b, X.y, IV0); FMA2(h0b, Y.y, IV3, h0b); FMA2(h0b, Z.y, IV6, h0b);
        MUL2(h1b, X.y, IV1); FMA2(h1b, Y.y, IV4, h1b); FMA2(h1b, Z.y, IV7, h1b);
        MUL2(h2b, X.y, IV2); FMA2(h2b, Y.y, IV5, h2b); FMA2(h2b, Z.y, IV8, h2b);
        ull r_, d0a, d1a, d2a, d0b, d1b, d2b;
        ADD2(r_, h0a, MG); ADD2(r_, r_, MGN); FMA2(d0a, r_, N1, h0a);
        ADD2(r_, h1a, MG); ADD2(r_, r_, MGN); FMA2(d1a, r_, N1, h1a);
        ADD2(r_, h2a, MG); ADD2(r_, r_, MGN); FMA2(d2a, r_, N1, h2a);
        ADD2(r_, h0b, MG); ADD2(r_, r_, MGN); FMA2(d0b, r_, N1, h0b);
        ADD2(r_, h1b, MG); ADD2(r_, r_, MGN); FMA2(d1b, r_, N1, h1b);
        ADD2(r_, h2b, MG); ADD2(r_, r_, MGN); FMA2(d2b, r_, N1, h2b);
        float2 f0a = upk2(d0a), f1a = upk2(d1a), f2a = upk2(d2a);
        float2 f0b = upk2(d0b), f1b = upk2(d1b), f2b = upk2(d2b);
        float e;
        e = fmaxf(fabsf(f0a.x), fmaxf(fabsf(f1a.x), fabsf(f2a.x)));
        c0 += (e < DIST) ? 1 : 0;
        e = fmaxf(fabsf(f0a.y), fmaxf(fabsf(f1a.y), fabsf(f2a.y)));
        c1 += (e < DIST) ? 1 : 0;
        e = fmaxf(fabsf(f0b.x), fmaxf(fabsf(f1b.x), fabsf(f2b.x)));
        c2 += (e < DIST) ? 1 : 0;
        e = fmaxf(fabsf(f0b.y), fmaxf(fabsf(f1b.y), fabsf(f2b.y)));
        c3 += (e < DIST) ? 1 : 0;
    }
    int cnt = (c0 + c1) + (c2 + c3);
    int m = k * NANG + al;
    ull key = 0ull;
    if (al < NANG)
        key = ((ull)(unsigned)cnt << 32) | (ull)(0xFFFFFFFFu - (unsigned)m);
    skey[a] = key;

    __syncthreads();  // uniform

    int grp = a >> 5;
    if (grp == 0 || grp == 3) {
        int base = (grp == 0) ? 0 : 96;
        int lane = a & 31;
        ull x = skey[base + lane];
        ull y = skey[base + lane + 32]; if (y > x) x = y;
        y = skey[base + lane + 64]; if (y > x) x = y;
        #pragma unroll
        for (int off = 16; off > 0; off >>= 1) {
            ull u = __shfl_xor_sync(0xffffffffu, x, off);
            if (u > x) x = u;
        }
        if (lane == 0) {
            g_key[b * NTOP + blockIdx.x * 2 + ((grp == 0) ? 0 : 1)] = x;
            __threadfence();
        }
    }

    __syncthreads();  // uniform; both fenced stores done

    if (a == 0) {
        unsigned prev = atomicAdd(&g_done_c[b], 1u);
        int last = (prev == (unsigned)(NTOP/2 - 1)) ? 1 : 0;
        if (last) g_done_c[b] = 0;
        s_last = last;
    }
    __syncthreads();  // uniform

    if (s_last && a < 32) {
        __threadfence();
        refine_batch(b, a, peaks, cell, lat, out, out_size);
    }
}

extern "C" void kernel_launch(void* const* d_in, const int* in_sizes, int n_in,
                              void* d_out, int out_size) {
    const float* peaks = (const float*)d_in[0];
    const float* cell  = (const float*)d_in[1];
    const float* lat   = (const float*)d_in[2];
    float* out = (float*)d_out;

    dim3 g1(NLB, NB);
    k_score<<<g1, SB>>>(peaks, cell, lat);
    k_select<<<NB, 1024>>>(cell, lat);
    dim3 g3(NTOP/2, NB);
    k_cand<<<g3, 192>>>(peaks, cell, lat, out, out_size);
}

// round 17
// speedup vs baseline: 1.0486x; 1.0486x over previous
#include <cuda_runtime.h>
#include <math.h>

#define NB    8
#define NPK   80
#define NL    100000
#define NTOP  200
#define NANG  90
#define DIST  0.2f
#define EPSF  1e-12f
#define BINS  81
#define SB    512          // k_score block: 16 warps; 4 blocks/SM = 64 warps (max)
#define NLB   196          // ceil(NL/SB)
#define MAGICF 12582912.0f // 1.5*2^23: (x+M)-M == rintf(x) for |x| < 2^22

typedef unsigned long long ull;

// ---- scratch (no allocation allowed) ----
__device__ unsigned char g_score[NB * NL + 128];   // padded; tail bytes stay zero-init
__device__ int           g_hist[NB * BINS];        // zero-init; k_select consumes+rezeros
__device__ int           g_topidx[NB * NTOP];
__device__ ull           g_key[NB * NTOP];         // per-(b,k) best (cnt, ~m) key
__device__ unsigned      g_done_c[NB];             // zero-init; last cand-block consumes+rezeros

// packed f32x2 helpers (elementwise IEEE RN)
#define MUL2(d,a,b)   asm("mul.rn.f32x2 %0,%1,%2;"    : "=l"(d) : "l"(a),"l"(b))
#define ADD2(d,a,b)   asm("add.rn.f32x2 %0,%1,%2;"    : "=l"(d) : "l"(a),"l"(b))
#define FMA2(d,a,b,c) asm("fma.rn.f32x2 %0,%1,%2,%3;" : "=l"(d) : "l"(a),"l"(b),"l"(c))
__device__ __forceinline__ ull pk2(float lo, float hi) {
    ull r; asm("mov.b64 %0,{%1,%2};" : "=l"(r) : "f"(lo), "f"(hi)); return r;
}
__device__ __forceinline__ float2 upk2(ull v) {
    float2 r; asm("mov.b64 {%0,%1},%2;" : "=f"(r.x), "=f"(r.y) : "l"(v)); return r;
}

// exact IEEE division a/b (Markstein-1 with correctly-rounded reciprocal)
__device__ __forceinline__ float div_x(float a, float b) {
    float r = __frcp_rn(b);
    float q0 = a * r;
    return fmaf(r, fmaf(-b, q0, a), q0);
}
__device__ __forceinline__ float div_xr(float a, float b, float r) {
    float q0 = a * r;
    return fmaf(r, fmaf(-b, q0, a), q0);
}

// cofactor inverse matching the JAX reference (zero matrix if |det|<1e-10)
__device__ __forceinline__ void inv3(const float* M, float* o) {
    float a=M[0],b=M[1],c=M[2],d=M[3],e=M[4],f=M[5],g=M[6],h=M[7],i=M[8];
    float det = a*(e*i-f*h) - b*(d*i-f*g) + c*(d*h-e*g);
    float invd = (fabsf(det) >= 1e-10f) ? __frcp_rn(det) : 0.0f;
    o[0]=(e*i-f*h)*invd; o[1]=(c*h-b*i)*invd; o[2]=(b*f-c*e)*invd;
    o[3]=(f*g-d*i)*invd; o[4]=(a*i-c*g)*invd; o[5]=(c*d-a*f)*invd;
    o[6]=(d*h-e*g)*invd; o[7]=(b*g-a*h)*invd; o[8]=(a*e-b*d)*invd;
}

// candidate 3x3 from (direction, angle index)
__device__ __forceinline__ void make_cand(const float* __restrict__ cell,
                                          float tx, float ty, float tz,
                                          int a, float* cd) {
    float c00 = cell[0], c01 = cell[1], c02 = cell[2];
    float snn = sqrtf(c00*c00 + c01*c01 + c02*c02) + EPSF;
    float rsn = __frcp_rn(snn);
    float sx = div_xr(c00, snn, rsn), sy = div_xr(c01, snn, rsn), sz = div_xr(c02, snn, rsn);
    float tnn = sqrtf(tx*tx + ty*ty + tz*tz) + EPSF;
    float rtn = __frcp_rn(tnn);
    float ux = div_xr(tx, tnn, rtn), uy = div_xr(ty, tnn, rtn), uz = div_xr(tz, tnn, rtn);
    float Vx = sy*uz - sz*uy;
    float Vy = sz*ux - sx*uz;
    float Vz = sx*uy - sy*ux;
    float C  = sx*ux + sy*uy + sz*uz;
    float S2 = Vx*Vx + Vy*Vy + Vz*Vz;
    float K[9] = {0.0f,-Vz,Vy,  Vz,0.0f,-Vx,  -Vy,Vx,0.0f};
    float KK[9];
    #pragma unroll
    for (int r = 0; r < 3; r++)
        #pragma unroll
        for (int c2 = 0; c2 < 3; c2++)
            KK[r*3+c2] = K[r*3+0]*K[0*3+c2] + K[r*3+1]*K[1*3+c2] + K[r*3+2]*K[2*3+c2];
    float fac = div_x(1.0f - C, S2 + EPSF);
    float R0[9];
    #pragma unroll
    for (int i = 0; i < 9; i++) {
        float Ii = (i == 0 || i == 4 || i == 8) ? 1.0f : 0.0f;
        R0[i] = (Ii + K[i]) + fac * KK[i];
    }
    float cells[9];
    #pragma unroll
    for (int r = 0; r < 3; r++)
        #pragma unroll
        for (int i = 0; i < 3; i++)
            cells[r*3+i] = R0[i*3+0]*cell[r*3+0] + R0[i*3+1]*cell[r*3+1] + R0[i*3+2]*cell[r*3+2];
    float A2[9] = {0.0f,-uz,uy,  uz,0.0f,-ux,  -uy,ux,0.0f};
    float AA[9];
    #pragma unroll
    for (int r = 0; r < 3; r++)
        #pragma unroll
        for (int c2 = 0; c2 < 3; c2++)
            AA[r*3+c2] = A2[r*3+0]*A2[0*3+c2] + A2[r*3+1]*A2[1*3+c2] + A2[r*3+2]*A2[2*3+c2];
    float alpha = (6.2831855f * (float)a) / 90.0f;
    float sv = sinf(alpha);
    float cv = 1.0f - cosf(alpha);
    float Rr[9];
    #pragma unroll
    for (int i = 0; i < 9; i++) {
        float Ii = (i == 0 || i == 4 || i == 8) ? 1.0f : 0.0f;
        Rr[i] = (Ii + sv * A2[i]) + cv * AA[i];
    }
    #pragma unroll
    for (int r = 0; r < 3; r++)
        #pragma unroll
        for (int i = 0; i < 3; i++)
            cd[r*3+i] = Rr[i*3+0]*cells[r*3+0] + Rr[i*3+1]*cells[r*3+1] + Rr[i*3+2]*cells[r*3+2];
}

// ============================================================
// Kernel 1: integer-ness score + folded histogram.
// Peaks pre-divided by scale0 at setup (output-identical, verified):
// inner loop = 12 packed FMA-pipe ops per 4 elements.
// ============================================================
__global__ void __launch_bounds__(SB, 4)
k_score(const float* __restrict__ peaks,
        const float* __restrict__ cell,
        const float* __restrict__ lat) {
    __shared__ __align__(16) float sx[NPK];
    __shared__ __align__(16) float sy[NPK];
    __shared__ __align__(16) float sz[NPK];
    __shared__ int shist[BINS];
    int tid = threadIdx.x;
    int b = blockIdx.y;

    float scale0 = sqrtf(cell[0]*cell[0] + cell[1]*cell[1] + cell[2]*cell[2]);
    if (tid < NPK) {
        const float* p = peaks + (b * NPK + tid) * 3;
        sx[tid] = p[0] / scale0;         // exact IEEE divide, hoisted
        sy[tid] = p[1] / scale0;
        sz[tid] = p[2] / scale0;
    }
    if (tid >= 128 && tid < 128 + BINS) shist[tid - 128] = 0;
    __syncthreads();

    int l = blockIdx.x * SB + tid;
    bool act = (l < NL);
    float lx = 0.f, ly = 0.f, lz = 0.f;
    if (act) { lx = lat[l*3+0]; ly = lat[l*3+1]; lz = lat[l*3+2]; }
    ull LX = pk2(lx, lx), LY = pk2(ly, ly), LZ = pk2(lz, lz);
    ull MG = pk2(MAGICF, MAGICF), MGN = pk2(-MAGICF, -MAGICF), N1 = pk2(-1.0f, -1.0f);

    const ulonglong2* px = (const ulonglong2*)sx;
    const ulonglong2* py = (const ulonglong2*)sy;
    const ulonglong2* pz = (const ulonglong2*)sz;
    int cnt = 0;
    #pragma unroll
    for (int j = 0; j < NPK/4; j++) {
        ulonglong2 X = px[j], Y = py[j], Z = pz[j];
        ull qa, qb;
        MUL2(qa, X.x, LX); FMA2(qa, Y.x, LY, qa); FMA2(qa, Z.x, LZ, qa);
        MUL2(qb, X.y, LX); FMA2(qb, Y.y, LY, qb); FMA2(qb, Z.y, LZ, qb);
        ull ra, rb, da, db;
        ADD2(ra, qa, MG); ADD2(ra, ra, MGN);
        ADD2(rb, qb, MG); ADD2(rb, rb, MGN);
        FMA2(da, ra, N1, qa);            // d = q - rint(q)
        FMA2(db, rb, N1, qb);
        float2 fa = upk2(da), fb = upk2(db);
        cnt += (fabsf(fa.x) < DIST) ? 1 : 0;
        cnt += (fabsf(fa.y) < DIST) ? 1 : 0;
        cnt += (fabsf(fb.x) < DIST) ? 1 : 0;
        cnt += (fabsf(fb.y) < DIST) ? 1 : 0;
    }
    if (act) {
        g_score[b * NL + l] = (unsigned char)cnt;
        atomicAdd(&shist[cnt], 1);
    }
    __syncthreads();
    if (tid < BINS) {
        int v = shist[tid];
        if (v) atomicAdd(&g_hist[b * BINS + tid], v);
    }
}

// ============================================================
// Kernel 2: exact top-200 per batch (jax.lax.top_k tie semantics).
// SIMD byte compares on the common path; exact order preserved.
// ============================================================
__global__ void k_select() {
    int b = blockIdx.x;
    int tid = threadIdx.x;
    int lane = tid & 31, wid = tid >> 5;
    __shared__ int sh[BINS];
    __shared__ int sel[256];
    __shared__ int warpsum[32];
    __shared__ int s_ss, s_na, s_ne, gtc;

    if (tid < BINS) { sh[tid] = g_hist[b * BINS + tid]; g_hist[b * BINS + tid] = 0; }
    if (tid == 0) gtc = 0;
    __syncthreads();
    if (tid == 0) {
        int cum = 0, na = 0, s;
        for (s = 80; s >= 0; s--) {
            na = cum;
            cum += sh[s];
            if (cum >= NTOP) break;
        }
        s_ss = s; s_na = na; s_ne = NTOP - na;
    }
    __syncthreads();
    int ss = s_ss, na = s_na, ne = s_ne;
    unsigned ssx4 = (unsigned)ss * 0x01010101u;

    const uint4* gp = (const uint4*)(g_score + (size_t)b * NL);
    bool own  = (tid < 782);
    bool full = (tid < 781);

    int eqc = 0;
    if (own) {
        #pragma unroll
        for (int u = 0; u < 8; u++) {
            uint4 v = gp[tid * 8 + u];
            unsigned ws[4] = {v.x, v.y, v.z, v.w};
            #pragma unroll
            for (int w = 0; w < 4; w++) {
                unsigned word = ws[w];
                if (full) {
                    unsigned gtm = __vcmpgtu4(word, ssx4);
                    if (gtm) {
                        #pragma unroll
                        for (int j = 0; j < 4; j++) {
                            if ((gtm >> (8*j)) & 0xff) {
                                int s = (word >> (8*j)) & 0xff;
                                int idx = tid * 128 + u * 16 + w * 4 + j;
                                int slot = atomicAdd(&gtc, 1);
                                sel[slot] = ((80 - s) << 17) | idx;
                            }
                        }
                    }
                    eqc += __popc(__vcmpeq4(word, ssx4)) >> 3;
                } else {
                    #pragma unroll
                    for (int j = 0; j < 4; j++) {
                        int idx = tid * 128 + u * 16 + w * 4 + j;
                        int s = (word >> (8*j)) & 0xff;
                        if (idx < NL) {
                            if (s > ss) {
                                int slot = atomicAdd(&gtc, 1);
                                sel[slot] = ((80 - s) << 17) | idx;
                            }
                            eqc += (s == ss) ? 1 : 0;
                        }
                    }
                }
            }
        }
    }
    int v = eqc;
    #pragma unroll
    for (int off = 1; off < 32; off <<= 1) {
        int u = __shfl_up_sync(0xffffffffu, v, off);
        if (lane >= off) v += u;
    }
    if (lane == 31) warpsum[wid] = v;
    __syncthreads();
    if (tid < 32) {
        int x = warpsum[tid], y = x;
        #pragma unroll
        for (int off = 1; off < 32; off <<= 1) {
            int u = __shfl_up_sync(0xffffffffu, x, off);
            if (tid >= off) x += u;
        }
        warpsum[tid] = x - y;
    }
    __syncthreads();
    int rank = warpsum[wid] + (v - eqc);

    if (own && eqc > 0 && rank < ne) {
        #pragma unroll
        for (int u = 0; u < 8; u++) {
            uint4 vv = gp[tid * 8 + u];
            unsigned ws[4] = {vv.x, vv.y, vv.z, vv.w};
            #pragma unroll
            for (int w = 0; w < 4; w++) {
                unsigned word = ws[w];
                unsigned eqm = __vcmpeq4(word, ssx4);
                if (eqm) {
                    #pragma unroll
                    for (int j = 0; j < 4; j++) {
                        if ((eqm >> (8*j)) & 0xff) {
                            int idx = tid * 128 + u * 16 + w * 4 + j;
                            if (full || idx < NL) {
                                if (rank < ne) sel[na + rank] = ((80 - ss) << 17) | idx;
                                rank++;
                            }
                        }
                    }
                }
            }
        }
    }
    if (tid >= NTOP && tid < 256) sel[tid] = 0x7FFFFFFF;
    __syncthreads();

    for (int size = 2; size <= 256; size <<= 1) {
        for (int stride = size >> 1; stride > 0; stride >>= 1) {
            if (tid < 256) {
                int partner = tid ^ stride;
                if (partner > tid) {
                    bool up = ((tid & size) == 0);
                    int x = sel[tid], y = sel[partner];
                    if ((x > y) == up) { sel[tid] = y; sel[partner] = x; }
                }
            }
            __syncthreads();
        }
    }
    if (tid < NTOP) g_topidx[b * NTOP + tid] = sel[tid] & 0x1FFFF;
}

// ============================================================
// refine for one batch: warp-collective (cold path).
// ============================================================
__device__ void refine_batch(int b, int lane,
                             const float* __restrict__ peaks,
                             const float* __restrict__ cell,
                             const float* __restrict__ lat,
                             float* __restrict__ out, int out_size) {
    ull best = 0ull;
    for (int k = lane; k < NTOP; k += 32) {
        ull u = __ldcg(&g_key[b * NTOP + k]);
        if (u > best) best = u;
    }
    #pragma unroll
    for (int off = 16; off > 0; off >>= 1) {
        ull u = __shfl_xor_sync(0xffffffffu, best, off);
        if (u > best) best = u;
    }
    int scount = (int)(best >> 32);
    int m = (int)(0xFFFFFFFFu - (unsigned)(best & 0xFFFFFFFFull));
    int kw = m / NANG, aw = m % NANG;

    int li = g_topidx[b * NTOP + kw];
    float tx = lat[li*3+0], ty = lat[li*3+1], tz = lat[li*3+2];
    float B[9];
    make_cand(cell, tx, ty, tz, aw, B);

    int l16 = lane & 15;
    float Px[5], Py[5], Pz[5];
    #pragma unroll
    for (int r = 0; r < 5; r++) {
        const float* p = peaks + (b * NPK + l16 + 16 * r) * 3;
        Px[r] = p[0]; Py[r] = p[1]; Pz[r] = p[2];
    }

    const float thrs[5] = {0.02f, 0.015375f, 0.01075f, 0.006125f, 0.0015f};
    #pragma unroll 1
    for (int t = 0; t < 5; t++) {
        float I[9];
        inv3(B, I);
        float acc[15];
        #pragma unroll
        for (int i = 0; i < 15; i++) acc[i] = 0.0f;
        #pragma unroll
        for (int r = 0; r < 5; r++) {
            float p0 = Px[r], p1 = Py[r], p2 = Pz[r];
            float h0 = rintf(p0*I[0] + p1*I[3] + p2*I[6]);
            float h1 = rintf(p0*I[1] + p1*I[4] + p2*I[7]);
            float h2 = rintf(p0*I[2] + p1*I[5] + p2*I[8]);
            float q0 = h0*B[0] + h1*B[3] + h2*B[6] - p0;
            float q1 = h0*B[1] + h1*B[4] + h2*B[7] - p1;
            float q2 = h0*B[2] + h1*B[5] + h2*B[8] - p2;
            float resid = sqrtf(q0*q0 + q1*q1 + q2*q2);
            if (resid < thrs[t]) {
                acc[0]+=h0*h0; acc[1]+=h0*h1; acc[2]+=h0*h2;
                acc[3]+=h1*h1; acc[4]+=h1*h2; acc[5]+=h2*h2;
                acc[6]+=h0*p0;  acc[7]+=h0*p1;  acc[8]+=h0*p2;
                acc[9]+=h1*p0;  acc[10]+=h1*p1; acc[11]+=h1*p2;
                acc[12]+=h2*p0; acc[13]+=h2*p1; acc[14]+=h2*p2;
            }
        }
        #pragma unroll
        for (int off = 8; off > 0; off >>= 1)
            #pragma unroll
            for (int i = 0; i < 15; i++)
                acc[i] += __shfl_xor_sync(0xffffffffu, acc[i], off);
        float XtX[9] = {acc[0],acc[1],acc[2], acc[1],acc[3],acc[4], acc[2],acc[4],acc[5]};
        float IX[9];
        inv3(XtX, IX);
        float nB[9];
        #pragma unroll
        for (int r = 0; r < 3; r++)
            #pragma unroll
            for (int d2 = 0; d2 < 3; d2++)
                nB[r*3+d2] = IX[r*3+0]*acc[6+0*3+d2] + IX[r*3+1]*acc[6+1*3+d2] + IX[r*3+2]*acc[6+2*3+d2];
        #pragma unroll
        for (int i = 0; i < 9; i++) B[i] = nB[i];
    }

    if (lane == 0) {
        float bn[3], cn[3], dc = 0.0f;
        for (int r = 0; r < 3; r++) {
            bn[r] = sqrtf(B[r*3]*B[r*3] + B[r*3+1]*B[r*3+1] + B[r*3+2]*B[r*3+2]);
            cn[r] = sqrtf(cell[r*3]*cell[r*3] + cell[r*3+1]*cell[r*3+1] + cell[r*3+2]*cell[r*3+2]);
            dc = fmaxf(dc, fabsf(bn[r] - cn[r]));
        }
        float Bn[9], Cn[9];
        for (int r = 0; r < 3; r++)
            for (int i = 0; i < 3; i++) {
                Bn[r*3+i] = B[r*3+i] / (bn[r] + EPSF);
                Cn[r*3+i] = cell[r*3+i] / (cn[r] + EPSF);
            }
        const float todeg = 57.29577951308232f;
        float da = 0.0f;
        const int pi_[3] = {0, 0, 1};
        const int pj_[3] = {1, 2, 2};
        for (int q = 0; q < 3; q++) {
            int i = pi_[q], j = pj_[q];
            float db = Bn[i*3]*Bn[j*3] + Bn[i*3+1]*Bn[j*3+1] + Bn[i*3+2]*Bn[j*3+2];
            float dl = Cn[i*3]*Cn[j*3] + Cn[i*3+1]*Cn[j*3+1] + Cn[i*3+2]*Cn[j*3+2];
            db = fminf(fmaxf(db, -1.0f), 1.0f);
            dl = fminf(fmaxf(dl, -1.0f), 1.0f);
            float ab = acosf(db) * todeg;
            float ac = acosf(dl) * todeg;
            da = fmaxf(da, fabsf(ab - ac));
        }
        float pen = dc*dc*dc + da*da*da;

        for (int i = 0; i < 9; i++) out[b*9 + i] = B[i];
        if (out_size >= 88) {
            out[72 + b] = (float)scount;
            out[80 + b] = pen;
        }
    }
}

// ============================================================
// Kernel 3: candidate scoring, 2 k's per block (192 threads),
// + per-batch last-block refine. Register-capped for occupancy.
// ============================================================
__global__ void __launch_bounds__(192, 6)
k_cand(const float* __restrict__ peaks,
       const float* __restrict__ cell,
       const float* __restrict__ lat,
       float* __restrict__ out, int out_size) {
    int b = blockIdx.y;
    int a = threadIdx.x;            // 0..191
    int kk = (a >= 96) ? 1 : 0;
    int al = a - 96 * kk;           // local angle 0..95 (90..95 garbage)
    int k  = blockIdx.x * 2 + kk;

    __shared__ __align__(16) float spx[NPK];
    __shared__ __align__(16) float spy[NPK];
    __shared__ __align__(16) float spz[NPK];
    __shared__ ull skey[192];
    __shared__ int s_last;

    if (a < NPK) {
        const float* p = peaks + (b * NPK + a) * 3;
        spx[a] = p[0]; spy[a] = p[1]; spz[a] = p[2];
    }

    int li = g_topidx[b * NTOP + k];
    float tx = lat[li*3+0], ty = lat[li*3+1], tz = lat[li*3+2];
    float cd[9];
    make_cand(cell, tx, ty, tz, al, cd);
    float iv[9];
    inv3(cd, iv);

    ull IV0 = pk2(iv[0], iv[0]), IV1 = pk2(iv[1], iv[1]), IV2 = pk2(iv[2], iv[2]);
    ull IV3 = pk2(iv[3], iv[3]), IV4 = pk2(iv[4], iv[4]), IV5 = pk2(iv[5], iv[5]);
    ull IV6 = pk2(iv[6], iv[6]), IV7 = pk2(iv[7], iv[7]), IV8 = pk2(iv[8], iv[8]);
    ull MG = pk2(MAGICF, MAGICF), MGN = pk2(-MAGICF, -MAGICF), N1 = pk2(-1.0f, -1.0f);

    __syncthreads();  // sp ready (uniform)

    const ulonglong2* px = (const ulonglong2*)spx;
    const ulonglong2* py = (const ulonglong2*)spy;
    const ulonglong2* pz = (const ulonglong2*)spz;
    int cnt = 0;
    #pragma unroll 5
    for (int j = 0; j < NPK/4; j++) {
        ulonglong2 X = px[j], Y = py[j], Z = pz[j];
        ull h0a, h1a, h2a, h0b, h1b, h2b;
        MUL2(h0a, X.x, IV0); FMA2(h0a, Y.x, IV3, h0a); FMA2(h0a, Z.x, IV6, h0a);
        MUL2(h1a, X.x, IV1); FMA2(h1a, Y.x, IV4, h1a); FMA2(h1a, Z.x, IV7, h1a);
        MUL2(h2a, X.x, IV2); FMA2(h2a, Y.x, IV5, h2a); FMA2(h2a, Z.x, IV8, h2a);
        MUL2(h0b, X.y, IV0); FMA2(h0b, Y.y, IV3, h0b); FMA2(h0b, Z.y, IV6, h0b);
        MUL2(h1b, X.y, IV1); FMA2(h1b, Y.y, IV4, h1b); FMA2(h1b, Z.y, IV7, h1b);
        MUL2(h2b, X.y, IV2); FMA2(h2b, Y.y, IV5, h2b); FMA2(h2b, Z.y, IV8, h2b);
        ull r_, d0a, d1a, d2a, d0b, d1b, d2b;
        ADD2(r_, h0a, MG); ADD2(r_, r_, MGN); FMA2(d0a, r_, N1, h0a);
        ADD2(r_, h1a, MG); ADD2(r_, r_, MGN); FMA2(d1a, r_, N1, h1a);
        ADD2(r_, h2a, MG); ADD2(r_, r_, MGN); FMA2(d2a, r_, N1, h2a);
        ADD2(r_, h0b, MG); ADD2(r_, r_, MGN); FMA2(d0b, r_, N1, h0b);
        ADD2(r_, h1b, MG); ADD2(r_, r_, MGN); FMA2(d1b, r_, N1, h1b);
        ADD2(r_, h2b, MG); ADD2(r_, r_, MGN); FMA2(d2b, r_, N1, h2b);
        float2 f0a = upk2(d0a), f1a = upk2(d1a), f2a = upk2(d2a);
        float2 f0b = upk2(d0b), f1b = upk2(d1b), f2b = upk2(d2b);
        float e;
        e = fmaxf(fabsf(f0a.x), fmaxf(fabsf(f1a.x), fabsf(f2a.x)));
        cnt += (e < DIST) ? 1 : 0;
        e = fmaxf(fabsf(f0a.y), fmaxf(fabsf(f1a.y), fabsf(f2a.y)));
        cnt += (e < DIST) ? 1 : 0;
        e = fmaxf(fabsf(f0b.x), fmaxf(fabsf(f1b.x), fabsf(f2b.x)));
        cnt += (e < DIST) ? 1 : 0;
        e = fmaxf(fabsf(f0b.y), fmaxf(fabsf(f1b.y), fabsf(f2b.y)));
        cnt += (e < DIST) ? 1 : 0;
    }
    int m = k * NANG + al;
    ull key = 0ull;
    if (al < NANG)
        key = ((ull)(unsigned)cnt << 32) | (ull)(0xFFFFFFFFu - (unsigned)m);
    skey[a] = key;

    __syncthreads();  // uniform

    // warps 0 and 3 reduce their k's 96 keys; writers fence their own stores
    int grp = a >> 5;
    if (grp == 0 || grp == 3) {
        int base = (grp == 0) ? 0 : 96;
        int lane = a & 31;
        ull x = skey[base + lane];
        ull y = skey[base + lane + 32]; if (y > x) x = y;
        y = skey[base + lane + 64]; if (y > x) x = y;
        #pragma unroll
        for (int off = 16; off > 0; off >>= 1) {
            ull u = __shfl_xor_sync(0xffffffffu, x, off);
            if (u > x) x = u;
        }
        if (lane == 0) {
            g_key[b * NTOP + blockIdx.x * 2 + ((grp == 0) ? 0 : 1)] = x;
            __threadfence();               // writer's own fence
        }
    }

    __syncthreads();  // uniform; both fenced stores done

    if (a == 0) {
        unsigned prev = atomicAdd(&g_done_c[b], 1u);
        int last = (prev == (unsigned)(NTOP/2 - 1)) ? 1 : 0;
        if (last) g_done_c[b] = 0;
        s_last = last;
    }
    __syncthreads();  // uniform

    if (s_last && a < 32) {
        __threadfence();                   // acquire other blocks' g_key
        refine_batch(b, a, peaks, cell, lat, out, out_size);
    }
}

extern "C" void kernel_launch(void* const* d_in, const int* in_sizes, int n_in,
                              void* d_out, int out_size) {
    const float* peaks = (const float*)d_in[0];
    const float* cell  = (const float*)d_in[1];
    const float* lat   = (const float*)d_in[2];
    float* out = (float*)d_out;

    dim3 g1(NLB, NB);
    k_score<<<g1, SB>>>(peaks, cell, lat);
    k_select<<<NB, 1024>>>();
    dim3 g3(NTOP/2, NB);
    k_cand<<<g3, 192>>>(peaks, cell, lat, out, out_size);
}